// round 10
// baseline (speedup 1.0000x reference)
#include <cuda_runtime.h>
#include <cstdint>

// out[dst] += x[src]. x: [N,64] f32, edge_index: [2,E] int32 on device.
//
// reset: cudaMemsetAsync nodes (no kernel). fill: bin edges by dst into
// fixed-capacity per-node lists. gather: ONE WARP PER NODE (32 float2 lanes;
// removes the max(deg0,deg1) pairing tax of 16-lane groups), round-6-proven
// 4-wide unconditional loop body, register accumulate, plain STG.64 stores.
// Overflow (prob ~1e-17) folded into gather. Fallback atomic path N > N_MAX.

#define N_MAX  50000
#define CAP    64
#define MAX_OF 65536

__device__ int g_cnt[N_MAX];
__device__ int g_lists[N_MAX * CAP];
__device__ int g_of_src[MAX_OF];
__device__ int g_of_dst[MAX_OF];
__device__ int g_of_count;

__device__ __forceinline__ void red_add_v4(float* p, float4 v) {
    asm volatile("red.global.add.v4.f32 [%0], {%1, %2, %3, %4};"
                 :: "l"(p), "f"(v.x), "f"(v.y), "f"(v.z), "f"(v.w)
                 : "memory");
}

__device__ __forceinline__ void acc2(float2& a, float2 v) {
    a.x += v.x; a.y += v.y;
}

// ---- phase 1: bin edges by dst (round-6 body) ----------------------------
__global__ void mp_fill_kernel(const int* __restrict__ ei, int E) {
    int g = blockIdx.x * blockDim.x + threadIdx.x;
    int e0 = g * 4;
    if (e0 >= E) return;

    int s[4], d[4];
    int m;
    if (e0 + 3 < E) {
        int4 sv = __ldg((const int4*)(ei + e0));
        int4 dv = __ldg((const int4*)(ei + E + e0));
        s[0] = sv.x; s[1] = sv.y; s[2] = sv.z; s[3] = sv.w;
        d[0] = dv.x; d[1] = dv.y; d[2] = dv.z; d[3] = dv.w;
        m = 4;
    } else {
        m = E - e0;
        for (int k = 0; k < m; ++k) {
            s[k] = __ldg(ei + e0 + k);
            d[k] = __ldg(ei + E + e0 + k);
        }
    }
    #pragma unroll
    for (int k = 0; k < 4; ++k) {
        if (k >= m) break;
        int p = atomicAdd(&g_cnt[d[k]], 1);
        if (p < CAP) {
            g_lists[d[k] * CAP + p] = s[k];
        } else {
            int o = atomicAdd(&g_of_count, 1);
            if (o < MAX_OF) { g_of_src[o] = s[k]; g_of_dst[o] = d[k]; }
        }
    }
}

// ---- phase 2: one warp per node, float2 lanes ----------------------------
__global__ void mp_gather_kernel(const float2* __restrict__ x,
                                 float2* __restrict__ out, int N) {
    int idx  = blockIdx.x * blockDim.x + threadIdx.x;
    int node = idx >> 5;        // one warp per node
    int h    = idx & 31;        // float2 lane within the 64-float row
    if (node >= N) return;

    int c = g_cnt[node];
    if (c > CAP) c = CAP;
    const int4* lst4 = (const int4*)(g_lists + node * CAP);

    float2 a0 = make_float2(0.f, 0.f);
    float2 a1 = make_float2(0.f, 0.f);
    float2 a2 = make_float2(0.f, 0.f);
    float2 a3 = make_float2(0.f, 0.f);

    int j = 0;
    for (; j + 3 < c; j += 4) {
        int4 s = __ldg(lst4 + (j >> 2));        // warp-uniform broadcast load
        float2 v0 = __ldg(x + s.x * 32 + h);    // 4 independent gather chains
        float2 v1 = __ldg(x + s.y * 32 + h);
        float2 v2 = __ldg(x + s.z * 32 + h);
        float2 v3 = __ldg(x + s.w * 32 + h);
        acc2(a0, v0); acc2(a1, v1); acc2(a2, v2); acc2(a3, v3);
    }
    if (j < c) {
        const int* lst = (const int*)lst4;
        for (; j < c; ++j)
            acc2(a0, __ldg(x + __ldg(lst + j) * 32 + h));
    }

    // Fold in overflow edges targeting this node (expected: none).
    int nof = g_of_count;
    if (nof > 0) {
        if (nof > MAX_OF) nof = MAX_OF;
        for (int i = 0; i < nof; ++i)
            if (g_of_dst[i] == node)
                acc2(a0, __ldg(x + g_of_src[i] * 32 + h));
    }

    acc2(a0, a1); acc2(a2, a3); acc2(a0, a2);
    out[node * 32 + h] = a0;
}

// ---- fallback (N > N_MAX): pure atomic path ------------------------------
__global__ void mp_zero_kernel(float4* __restrict__ out, int n4) {
    int i = blockIdx.x * blockDim.x + threadIdx.x;
    if (i < n4) out[i] = make_float4(0.f, 0.f, 0.f, 0.f);
}

__global__ void mp_scatter_kernel(const float4* __restrict__ x,
                                  const int* __restrict__ ei,
                                  float* __restrict__ out, int E) {
    int idx = blockIdx.x * blockDim.x + threadIdx.x;
    int e = idx >> 4, q = idx & 15;
    if (e >= E) return;
    int src = __ldg(ei + e);
    int dst = __ldg(ei + E + e);
    float4 v = __ldg(x + src * 16 + q);
    red_add_v4(out + dst * 64 + q * 4, v);
}

extern "C" void kernel_launch(void* const* d_in, const int* in_sizes, int n_in,
                              void* d_out, int out_size) {
    const float* xf = (const float*)d_in[0];
    const int* ei = (const int*)d_in[1];
    float* out = (float*)d_out;

    int E = in_sizes[1] / 2;          // 800000
    int N = in_sizes[0] / 64;         // 50000

    if (N <= N_MAX) {
        // reset via graph-capturable memset nodes (no kernel launch)
        void* p_cnt = nullptr;
        void* p_of  = nullptr;
        cudaGetSymbolAddress(&p_cnt, g_cnt);
        cudaGetSymbolAddress(&p_of,  g_of_count);
        cudaMemsetAsync(p_cnt, 0, (size_t)N * sizeof(int));
        cudaMemsetAsync(p_of,  0, sizeof(int));

        int groups = (E + 3) / 4;
        mp_fill_kernel<<<(groups + 255) / 256, 256>>>(ei, E);

        long long work = (long long)N * 32;
        mp_gather_kernel<<<(int)((work + 255) / 256), 256>>>(
            (const float2*)xf, (float2*)out, N);
    } else {
        int n4 = out_size / 4;
        mp_zero_kernel<<<(n4 + 255) / 256, 256>>>((float4*)out, n4);
        long long work = (long long)E * 16;
        mp_scatter_kernel<<<(int)((work + 255) / 256), 256>>>(
            (const float4*)xf, ei, out, E);
    }
}

// round 12
// speedup vs baseline: 1.0508x; 1.0508x over previous
#include <cuda_runtime.h>
#include <cstdint>

// out[dst] += x[src]. x: [N,64] f32, edge_index: [2,E] int32 on device.
//
// reset: cudaMemsetAsync graph nodes (no kernel).
// fill:  bin edges by dst; 2 edges/thread (400k threads for ATOMG latency
//        hiding), both slot atomics hoisted into independent chains.
// gather: 16 float4 lanes per node (round-6 proven body), register
//        accumulate, one plain STG.128 per quad; overflow (prob ~1e-17)
//        folded in before the store. Fallback pure-atomic path N > N_MAX.

#define N_MAX  50000
#define CAP    64
#define MAX_OF 65536

__device__ int g_cnt[N_MAX];
__device__ int g_lists[N_MAX * CAP];
__device__ int g_of_src[MAX_OF];
__device__ int g_of_dst[MAX_OF];
__device__ int g_of_count;

__device__ __forceinline__ void red_add_v4(float* p, float4 v) {
    asm volatile("red.global.add.v4.f32 [%0], {%1, %2, %3, %4};"
                 :: "l"(p), "f"(v.x), "f"(v.y), "f"(v.z), "f"(v.w)
                 : "memory");
}

__device__ __forceinline__ void acc_add(float4& a, float4 v) {
    a.x += v.x; a.y += v.y; a.z += v.z; a.w += v.w;
}

// ---- phase 1: bin edges by dst (2 edges/thread, hoisted atomics) ---------
__global__ void mp_fill_kernel(const int* __restrict__ ei, int E) {
    int g = blockIdx.x * blockDim.x + threadIdx.x;
    int e0 = g * 2;
    if (e0 >= E) return;

    if (e0 + 1 < E) {
        int2 sv = __ldg((const int2*)(ei + e0));
        int2 dv = __ldg((const int2*)(ei + E + e0));
        // Two independent atomic chains in flight.
        int p0 = atomicAdd(&g_cnt[dv.x], 1);
        int p1 = atomicAdd(&g_cnt[dv.y], 1);
        if (p0 < CAP) {
            g_lists[dv.x * CAP + p0] = sv.x;
        } else {
            int o = atomicAdd(&g_of_count, 1);
            if (o < MAX_OF) { g_of_src[o] = sv.x; g_of_dst[o] = dv.x; }
        }
        if (p1 < CAP) {
            g_lists[dv.y * CAP + p1] = sv.y;
        } else {
            int o = atomicAdd(&g_of_count, 1);
            if (o < MAX_OF) { g_of_src[o] = sv.y; g_of_dst[o] = dv.y; }
        }
    } else {
        int s = __ldg(ei + e0);
        int d = __ldg(ei + E + e0);
        int p = atomicAdd(&g_cnt[d], 1);
        if (p < CAP) {
            g_lists[d * CAP + p] = s;
        } else {
            int o = atomicAdd(&g_of_count, 1);
            if (o < MAX_OF) { g_of_src[o] = s; g_of_dst[o] = d; }
        }
    }
}

// ---- phase 2: gather-accumulate (+inline overflow), plain store ----------
__global__ void mp_gather_kernel(const float4* __restrict__ x,
                                 float4* __restrict__ out, int N) {
    int idx = blockIdx.x * blockDim.x + threadIdx.x;
    int node = idx >> 4;
    int q    = idx & 15;
    if (node >= N) return;

    int c = g_cnt[node];
    if (c > CAP) c = CAP;
    const int4* lst4 = (const int4*)(g_lists + node * CAP);

    float4 a0 = make_float4(0.f, 0.f, 0.f, 0.f);
    float4 a1 = make_float4(0.f, 0.f, 0.f, 0.f);
    float4 a2 = make_float4(0.f, 0.f, 0.f, 0.f);
    float4 a3 = make_float4(0.f, 0.f, 0.f, 0.f);

    int j = 0;
    for (; j + 3 < c; j += 4) {
        int4 s = __ldg(lst4 + (j >> 2));       // 4 src indices, one LDG
        float4 v0 = __ldg(x + s.x * 16 + q);   // 4 independent gather chains
        float4 v1 = __ldg(x + s.y * 16 + q);
        float4 v2 = __ldg(x + s.z * 16 + q);
        float4 v3 = __ldg(x + s.w * 16 + q);
        acc_add(a0, v0); acc_add(a1, v1); acc_add(a2, v2); acc_add(a3, v3);
    }
    if (j < c) {
        const int* lst = (const int*)lst4;
        for (; j < c; ++j)
            acc_add(a0, __ldg(x + __ldg(lst + j) * 16 + q));
    }

    // Fold in overflow edges targeting this node (expected: none).
    int nof = g_of_count;
    if (nof > 0) {
        if (nof > MAX_OF) nof = MAX_OF;
        for (int i = 0; i < nof; ++i)
            if (g_of_dst[i] == node)
                acc_add(a0, __ldg(x + g_of_src[i] * 16 + q));
    }

    acc_add(a0, a1); acc_add(a2, a3); acc_add(a0, a2);
    out[node * 16 + q] = a0;
}

// ---- fallback (N > N_MAX): pure atomic path ------------------------------
__global__ void mp_zero_kernel(float4* __restrict__ out, int n4) {
    int i = blockIdx.x * blockDim.x + threadIdx.x;
    if (i < n4) out[i] = make_float4(0.f, 0.f, 0.f, 0.f);
}

__global__ void mp_scatter_kernel(const float4* __restrict__ x,
                                  const int* __restrict__ ei,
                                  float* __restrict__ out, int E) {
    int idx = blockIdx.x * blockDim.x + threadIdx.x;
    int e = idx >> 4, q = idx & 15;
    if (e >= E) return;
    int src = __ldg(ei + e);
    int dst = __ldg(ei + E + e);
    float4 v = __ldg(x + src * 16 + q);
    red_add_v4(out + dst * 64 + q * 4, v);
}

extern "C" void kernel_launch(void* const* d_in, const int* in_sizes, int n_in,
                              void* d_out, int out_size) {
    const float4* x = (const float4*)d_in[0];
    const int* ei = (const int*)d_in[1];
    float* out = (float*)d_out;

    int E = in_sizes[1] / 2;          // 800000
    int N = in_sizes[0] / 64;         // 50000

    if (N <= N_MAX) {
        // Resolve scratch addresses once; capture path only enqueues nodes.
        static void* p_cnt = nullptr;
        static void* p_of  = nullptr;
        if (p_cnt == nullptr) {
            cudaGetSymbolAddress(&p_cnt, g_cnt);
            cudaGetSymbolAddress(&p_of,  g_of_count);
        }
        cudaMemsetAsync(p_cnt, 0, (size_t)N * sizeof(int));
        cudaMemsetAsync(p_of,  0, sizeof(int));

        int pairs = (E + 1) / 2;
        mp_fill_kernel<<<(pairs + 511) / 512, 512>>>(ei, E);

        long long work = (long long)N * 16;
        mp_gather_kernel<<<(int)((work + 255) / 256), 256>>>(x, (float4*)out, N);
    } else {
        int n4 = out_size / 4;
        mp_zero_kernel<<<(n4 + 255) / 256, 256>>>((float4*)out, n4);
        long long work = (long long)E * 16;
        mp_scatter_kernel<<<(int)((work + 255) / 256), 256>>>(x, ei, out, E);
    }
}

// round 13
// speedup vs baseline: 1.1646x; 1.1083x over previous
#include <cuda_runtime.h>
#include <cstdint>

// out[dst] += x[src]. x: [N,64] f32, edge_index: [2,E] int32 on device.
//
// reset kernel -> fill (bin by dst, 4 edges/thread) -> gather (16 float4
// lanes/node, register accumulate, plain STG.128). Gather's scalar tail is
// replaced by ONE masked 4-wide iteration: loads the full int4 slot group
// (always in-bounds; slots beyond c hold valid node ids from zero-init or a
// previous identical fill) and zero-weights out-of-range lanes — removes the
// serial dependent tail chain (~450cyc/edge) present since round 5.
// Overflow (prob ~1e-17) folded into gather. Fallback atomic path N > N_MAX.

#define N_MAX  50000
#define CAP    64
#define MAX_OF 65536

__device__ int g_cnt[N_MAX];
__device__ int g_lists[N_MAX * CAP];
__device__ int g_of_src[MAX_OF];
__device__ int g_of_dst[MAX_OF];
__device__ int g_of_count;

__device__ __forceinline__ void red_add_v4(float* p, float4 v) {
    asm volatile("red.global.add.v4.f32 [%0], {%1, %2, %3, %4};"
                 :: "l"(p), "f"(v.x), "f"(v.y), "f"(v.z), "f"(v.w)
                 : "memory");
}

__device__ __forceinline__ void acc_add(float4& a, float4 v) {
    a.x += v.x; a.y += v.y; a.z += v.z; a.w += v.w;
}

__device__ __forceinline__ void acc_fma(float4& a, float w, float4 v) {
    a.x = fmaf(w, v.x, a.x); a.y = fmaf(w, v.y, a.y);
    a.z = fmaf(w, v.z, a.z); a.w = fmaf(w, v.w, a.w);
}

// ---- phase 0: reset counters --------------------------------------------
__global__ void mp_reset_kernel(int N) {
    int i = blockIdx.x * blockDim.x + threadIdx.x;
    if (i < N) g_cnt[i] = 0;
    if (i == 0) g_of_count = 0;
}

// ---- phase 1: bin edges by dst (4 edges per thread, int4 index loads) ----
__global__ void mp_fill_kernel(const int* __restrict__ ei, int E) {
    int g = blockIdx.x * blockDim.x + threadIdx.x;
    int e0 = g * 4;
    if (e0 >= E) return;

    int s[4], d[4];
    int m;
    if (e0 + 3 < E) {
        int4 sv = __ldg((const int4*)(ei + e0));
        int4 dv = __ldg((const int4*)(ei + E + e0));
        s[0] = sv.x; s[1] = sv.y; s[2] = sv.z; s[3] = sv.w;
        d[0] = dv.x; d[1] = dv.y; d[2] = dv.z; d[3] = dv.w;
        m = 4;
    } else {
        m = E - e0;
        for (int k = 0; k < m; ++k) {
            s[k] = __ldg(ei + e0 + k);
            d[k] = __ldg(ei + E + e0 + k);
        }
    }
    #pragma unroll
    for (int k = 0; k < 4; ++k) {
        if (k >= m) break;
        int p = atomicAdd(&g_cnt[d[k]], 1);
        if (p < CAP) {
            g_lists[d[k] * CAP + p] = s[k];
        } else {
            int o = atomicAdd(&g_of_count, 1);
            if (o < MAX_OF) { g_of_src[o] = s[k]; g_of_dst[o] = d[k]; }
        }
    }
}

// ---- phase 2: gather-accumulate (+inline overflow), plain store ----------
__global__ void mp_gather_kernel(const float4* __restrict__ x,
                                 float4* __restrict__ out, int N) {
    int idx = blockIdx.x * blockDim.x + threadIdx.x;
    int node = idx >> 4;
    int q    = idx & 15;
    if (node >= N) return;

    int c = g_cnt[node];
    if (c > CAP) c = CAP;
    const int4* lst4 = (const int4*)(g_lists + node * CAP);

    float4 a0 = make_float4(0.f, 0.f, 0.f, 0.f);
    float4 a1 = make_float4(0.f, 0.f, 0.f, 0.f);
    float4 a2 = make_float4(0.f, 0.f, 0.f, 0.f);
    float4 a3 = make_float4(0.f, 0.f, 0.f, 0.f);

    int j = 0;
    for (; j + 3 < c; j += 4) {
        int4 s = __ldg(lst4 + (j >> 2));       // 4 src indices, one LDG
        float4 v0 = __ldg(x + s.x * 16 + q);   // 4 independent gather chains
        float4 v1 = __ldg(x + s.y * 16 + q);
        float4 v2 = __ldg(x + s.z * 16 + q);
        float4 v3 = __ldg(x + s.w * 16 + q);
        acc_add(a0, v0); acc_add(a1, v1); acc_add(a2, v2); acc_add(a3, v3);
    }
    if (j < c) {
        // Masked 4-wide tail: full int4 group is always in-bounds and holds
        // valid node ids; lanes >= c contribute with weight 0.
        int4 s = __ldg(lst4 + (j >> 2));
        float w0 = (j + 0 < c) ? 1.f : 0.f;
        float w1 = (j + 1 < c) ? 1.f : 0.f;
        float w2 = (j + 2 < c) ? 1.f : 0.f;
        float w3 = (j + 3 < c) ? 1.f : 0.f;
        float4 v0 = __ldg(x + s.x * 16 + q);
        float4 v1 = __ldg(x + s.y * 16 + q);
        float4 v2 = __ldg(x + s.z * 16 + q);
        float4 v3 = __ldg(x + s.w * 16 + q);
        acc_fma(a0, w0, v0); acc_fma(a1, w1, v1);
        acc_fma(a2, w2, v2); acc_fma(a3, w3, v3);
    }

    // Fold in overflow edges targeting this node (expected: none).
    int nof = g_of_count;
    if (nof > 0) {
        if (nof > MAX_OF) nof = MAX_OF;
        for (int i = 0; i < nof; ++i)
            if (g_of_dst[i] == node)
                acc_add(a0, __ldg(x + g_of_src[i] * 16 + q));
    }

    acc_add(a0, a1); acc_add(a2, a3); acc_add(a0, a2);
    out[node * 16 + q] = a0;
}

// ---- fallback (N > N_MAX): pure atomic path ------------------------------
__global__ void mp_zero_kernel(float4* __restrict__ out, int n4) {
    int i = blockIdx.x * blockDim.x + threadIdx.x;
    if (i < n4) out[i] = make_float4(0.f, 0.f, 0.f, 0.f);
}

__global__ void mp_scatter_kernel(const float4* __restrict__ x,
                                  const int* __restrict__ ei,
                                  float* __restrict__ out, int E) {
    int idx = blockIdx.x * blockDim.x + threadIdx.x;
    int e = idx >> 4, q = idx & 15;
    if (e >= E) return;
    int src = __ldg(ei + e);
    int dst = __ldg(ei + E + e);
    float4 v = __ldg(x + src * 16 + q);
    red_add_v4(out + dst * 64 + q * 4, v);
}

extern "C" void kernel_launch(void* const* d_in, const int* in_sizes, int n_in,
                              void* d_out, int out_size) {
    const float4* x = (const float4*)d_in[0];
    const int* ei = (const int*)d_in[1];
    float* out = (float*)d_out;

    int E = in_sizes[1] / 2;          // 800000
    int N = in_sizes[0] / 64;         // 50000

    if (N <= N_MAX) {
        mp_reset_kernel<<<(N + 255) / 256, 256>>>(N);
        int groups = (E + 3) / 4;
        mp_fill_kernel<<<(groups + 255) / 256, 256>>>(ei, E);
        long long work = (long long)N * 16;
        mp_gather_kernel<<<(int)((work + 255) / 256), 256>>>(x, (float4*)out, N);
    } else {
        int n4 = out_size / 4;
        mp_zero_kernel<<<(n4 + 255) / 256, 256>>>((float4*)out, n4);
        long long work = (long long)E * 16;
        mp_scatter_kernel<<<(int)((work + 255) / 256), 256>>>(x, ei, out, E);
    }
}